// round 2
// baseline (speedup 1.0000x reference)
#include <cuda_runtime.h>

// Conv2D 4096x4096 (*) 15x15 valid -> 4082x4082, fp32.
// Register-blocked SIMT kernel: 128x64 output tile / block, 256 threads,
// 8x4 outputs per thread. Designed to be FFMA-bound (~64 FMA/cyc/SM).
// (Round 2 resubmit: R1 bench was an infra failure, kernel unchanged.)

#define HGT 4096
#define WID 4096
#define KH  15
#define KW  15
#define OH  (HGT - KH + 1)   // 4082
#define OW  (WID - KW + 1)   // 4082

#define TW  128   // output tile width per block
#define TH  64    // output tile height per block
#define RX  4     // outputs per thread, x
#define RY  8     // outputs per thread, y
#define SW  144   // smem tile pitch in floats (142 needed, pad to mult of 16)
#define SH  (TH + KH - 1)   // 78 rows

__global__ __launch_bounds__(256, 2)
void conv2d15_kernel(const float* __restrict__ x,
                     const float* __restrict__ w,
                     const float* __restrict__ bias,
                     float* __restrict__ out) {
    __shared__ float tile[SH][SW];
    __shared__ float swt[KH * KW];

    const int tx  = threadIdx.x;          // 0..31
    const int ty  = threadIdx.y;          // 0..7
    const int tid = ty * 32 + tx;         // 0..255
    const int col0 = blockIdx.x * TW;
    const int row0 = blockIdx.y * TH;

    if (tid < KH * KW) swt[tid] = w[tid];

    // ---- load input tile (SH x SW floats) with float4, zero-fill OOB ----
    const int NV4 = SW / 4;               // 36 float4 per row
    for (int idx = tid; idx < SH * NV4; idx += 256) {
        int r  = idx / NV4;
        int c4 = idx - r * NV4;
        int gr = row0 + r;
        int gc = col0 + c4 * 4;
        float4 v;
        if (gr < HGT && gc + 3 < WID) {
            v = *(const float4*)(x + (size_t)gr * WID + gc);
        } else {
            v.x = (gr < HGT && gc + 0 < WID) ? x[(size_t)gr * WID + gc + 0] : 0.f;
            v.y = (gr < HGT && gc + 1 < WID) ? x[(size_t)gr * WID + gc + 1] : 0.f;
            v.z = (gr < HGT && gc + 2 < WID) ? x[(size_t)gr * WID + gc + 2] : 0.f;
            v.w = (gr < HGT && gc + 3 < WID) ? x[(size_t)gr * WID + gc + 3] : 0.f;
        }
        *(float4*)&tile[r][c4 * 4] = v;
    }
    __syncthreads();

    // ---- compute: each thread produces RY x RX outputs ----
    float acc[RY][RX];
    #pragma unroll
    for (int i = 0; i < RY; i++)
        #pragma unroll
        for (int j = 0; j < RX; j++)
            acc[i][j] = 0.f;

    const int txc = tx * RX;              // thread's first output col inside tile
    const int tyr = ty * RY;              // thread's first output row inside tile

    #pragma unroll 1
    for (int ky = 0; ky < KH; ky++) {
        float wrow[KW];
        #pragma unroll
        for (int kx = 0; kx < KW; kx++) wrow[kx] = swt[ky * KW + kx];

        #pragma unroll
        for (int i = 0; i < RY; i++) {
            const int r = tyr + i + ky;
            // 20-float window: cols [txc, txc+19], need txc..txc+17.
            // 5 conflict-free LDS.128 (txc is 16B-aligned, SW mult of 4).
            float win[20];
            const float4* p = (const float4*)&tile[r][txc];
            #pragma unroll
            for (int q = 0; q < 5; q++) {
                float4 v = p[q];
                win[q * 4 + 0] = v.x;
                win[q * 4 + 1] = v.y;
                win[q * 4 + 2] = v.z;
                win[q * 4 + 3] = v.w;
            }
            #pragma unroll
            for (int kx = 0; kx < KW; kx++) {
                const float wv = wrow[kx];
                #pragma unroll
                for (int j = 0; j < RX; j++)
                    acc[i][j] = fmaf(wv, win[kx + j], acc[i][j]);
            }
        }
    }

    // ---- store with bias, guarded at right/bottom edges ----
    const float b = bias[0];
    const int ocol = col0 + txc;
    #pragma unroll
    for (int i = 0; i < RY; i++) {
        const int orow = row0 + tyr + i;
        if (orow < OH) {
            #pragma unroll
            for (int j = 0; j < RX; j++) {
                const int oc = ocol + j;
                if (oc < OW)
                    out[(size_t)orow * OW + oc] = acc[i][j] + b;
            }
        }
    }
}

extern "C" void kernel_launch(void* const* d_in, const int* in_sizes, int n_in,
                              void* d_out, int out_size) {
    const float* x    = (const float*)d_in[0];
    const float* w    = (const float*)d_in[1];
    const float* bias = (const float*)d_in[2];
    float* out        = (float*)d_out;

    dim3 block(32, 8, 1);
    dim3 grid((OW + TW - 1) / TW, (OH + TH - 1) / TH, 1);  // (32, 64)
    conv2d15_kernel<<<grid, block>>>(x, w, bias, out);
}